// round 14
// baseline (speedup 1.0000x reference)
#include <cuda_runtime.h>

#define FULL 0xFFFFFFFFu
#define NUM_E 256
#define TOPK 8

// monotonic float -> u32 key (fallback path only)
__device__ __forceinline__ unsigned f2key(float f) {
    unsigned u = __float_as_uint(f);
    return u ^ ((unsigned)((int)u >> 31) | 0x80000000u);
}
__device__ __forceinline__ float sigmoidf_fast(float x) {
    return __fdividef(1.0f, 1.0f + __expf(-x));
}

// Per-lane sorted top-3 keys for one token row (proven R9 network).
// key = raw float bits of (sigmoid+bias), low 8 bits = expert index
// g = (lane<<2) | (j&3) | ((j>>2)<<7)  (disjoint bit fields, unique, decode = &255)
__device__ __forceinline__ void build_top3(float4 x0, float4 x1,
                                           float4 bb0, float4 bb1, int lane,
                                           int& c0, int& c1, int& c2)
{
    float xs[8] = {x0.x, x0.y, x0.z, x0.w, x1.x, x1.y, x1.z, x1.w};
    float bs[8] = {bb0.x, bb0.y, bb0.z, bb0.w, bb1.x, bb1.y, bb1.z, bb1.w};
    const unsigned lane4 = (unsigned)lane << 2;
    int k[8];
#pragma unroll
    for (int j = 0; j < 8; j++) {
        float s = sigmoidf_fast(xs[j]);
        unsigned ub  = __float_as_uint(s + bs[j]);
        unsigned fld = lane4 | (unsigned)((j & 3) | ((j >> 2) << 7));
        k[j] = (int)((ub & 0xFFFFFF00u) | fld);
    }
#define PAIR(a, b) { int hi = max(k[a], k[b]); int lo = min(k[a], k[b]); k[a] = hi; k[b] = lo; }
    PAIR(0,1) PAIR(2,3) PAIR(4,5) PAIR(6,7)
#undef PAIR
    int a0, a1, a2, b0, b1, b2;
    {
        int h = max(k[0], k[2]), t = min(k[0], k[2]);
        a0 = h; a1 = max(k[1], t); a2 = max(min(k[1], t), k[3]);
    }
    {
        int h = max(k[4], k[6]), t = min(k[4], k[6]);
        b0 = h; b1 = max(k[5], t); b2 = max(min(k[5], t), k[7]);
    }
    c0 = max(a0, b2);
    c1 = max(a1, b1);
    c2 = max(a2, b0);
    { int a = c0, b = c1; c0 = max(a, b); c1 = min(a, b); }
    { int a = c0, b = c2; c0 = max(a, b); c2 = min(a, b); }
    { int a = c1, b = c2; c1 = max(a, b); c2 = min(a, b); }
}

// Proven exact fallback for one token (full-precision keys, Batcher + payload).
// Warp-uniform entry; rare (~0.4% of tokens).
__device__ void exact_route_warp(const float* __restrict__ rowp,
                                 const float* __restrict__ bias,
                                 float* __restrict__ oi,
                                 float* __restrict__ ow,
                                 int lane)
{
    const float4* row4 = reinterpret_cast<const float4*>(rowp);
    const float4* b4   = reinterpret_cast<const float4*>(bias);
    float4 y0 = row4[lane];              // L1/L2-hot reloads
    float4 y1 = row4[lane + 32];
    float4 cb0 = __ldg(b4 + lane);
    float4 cb1 = __ldg(b4 + lane + 32);
    float ys[8] = {y0.x, y0.y, y0.z, y0.w, y1.x, y1.y, y1.z, y1.w};
    float cs[8] = {cb0.x, cb0.y, cb0.z, cb0.w, cb1.x, cb1.y, cb1.z, cb1.w};

    unsigned fk[8], pj[8];
#pragma unroll
    for (int j = 0; j < 8; j++) {
        float s = sigmoidf_fast(ys[j]);
        fk[j] = f2key(s + cs[j]);
        pj[j] = (unsigned)j;
    }
#define CEP(a, b) do {                                    \
        unsigned ka = fk[a], kb = fk[b];                  \
        bool p = kb > ka;                                 \
        fk[a] = p ? kb : ka;  fk[b] = p ? ka : kb;        \
        unsigned pa = pj[a], pb = pj[b];                  \
        pj[a] = p ? pb : pa;  pj[b] = p ? pa : pb;        \
    } while (0)
    CEP(0,1); CEP(2,3); CEP(4,5); CEP(6,7);
    CEP(0,2); CEP(1,3); CEP(1,2);
    CEP(4,6); CEP(5,7); CEP(5,6);
    CEP(0,4); CEP(1,5); CEP(2,6); CEP(3,7);
    CEP(2,4); CEP(3,5);
    CEP(1,2); CEP(3,4); CEP(5,6);
#undef CEP
    unsigned pjpack = 0;
#pragma unroll
    for (int j = 0; j < 8; j++) pjpack |= pj[j] << (4 * j);

    int g = 0;
#pragma unroll
    for (int r = 0; r < TOPK; r++) {
        unsigned wb  = __reduce_max_sync(FULL, fk[0]);
        unsigned msk = __ballot_sync(FULL, fk[0] == wb);
        int src = __ffs(msk) - 1;

        int p0 = (int)(pjpack & 7u);
        int gg = 4 * lane + p0 + ((p0 & 4) ? 124 : 0);
        gg = __shfl_sync(FULL, gg, src);
        if (lane == r) g = gg;

        bool q = (lane == src);
        fk[0] = q ? fk[1] : fk[0];
        fk[1] = q ? fk[2] : fk[1];
        fk[2] = q ? fk[3] : fk[2];
        fk[3] = q ? fk[4] : fk[3];
        fk[4] = q ? fk[5] : fk[4];
        fk[5] = q ? fk[6] : fk[5];
        fk[6] = q ? fk[7] : fk[6];
        pjpack = q ? (pjpack >> 4) : pjpack;
    }

    if (lane < TOPK) {
        float x = __ldg(rowp + g);
        float wgt = sigmoidf_fast(x);
        float sum = wgt;
#pragma unroll
        for (int off = 4; off; off >>= 1)
            sum += __shfl_xor_sync(0xFFu, sum, off);
        float wn = wgt * __fdividef(1.0f, sum + 1e-20f);
        oi[lane] = (float)g;
        ow[lane] = wn;
    }
}

__global__ void __launch_bounds__(256)   // NO min-blocks cap: let ptxas pick regs (~36-40)
moe_route_kernel(const float* __restrict__ logits,
                 const float* __restrict__ bias,
                 float* __restrict__ out_idx,   // indices stored as float32 values
                 float* __restrict__ out_w,
                 int T)
{
    const int lane = threadIdx.x & 31;
    const int wgl  = (int)((blockIdx.x * blockDim.x + threadIdx.x) >> 5);
    const int tokA = 2 * wgl;
    const int tokB = tokA + 1;
    if (tokA >= T) return;                    // uniform per warp
    const bool hasB = (tokB < T);

    const float4* rowA4 = reinterpret_cast<const float4*>(logits) + (size_t)tokA * (NUM_E / 4);
    const float4* rowB4 = hasB ? rowA4 + (NUM_E / 4) : rowA4;    // safe dummy if odd T
    const float4* b4 = reinterpret_cast<const float4*>(bias);

    // front-batched loads: 4 row LDG.128 + 2 bias LDG.128 (MLP=6)
    float4 xA0 = rowA4[lane];
    float4 xA1 = rowA4[lane + 32];
    float4 xB0 = rowB4[lane];
    float4 xB1 = rowB4[lane + 32];
    float4 bb0 = __ldg(b4 + lane);            // bias serves both tokens
    float4 bb1 = __ldg(b4 + lane + 32);

    // ---- per-lane sorted top-3 for both tokens ----
    int cA0, cA1, cA2, cB0, cB1, cB2;
    build_top3(xA0, xA1, bb0, bb1, lane, cA0, cA1, cA2);
    build_top3(xB0, xB1, bb0, bb1, lane, cB0, cB1, cB2);

    // ---- interleaved extraction: two independent REDUX chains overlap ----
    // In-loop keep: lane r holds token A's round-r winner, lane 8+r token B's.
    // Depth-2 chain: a lane's 4th win re-emits its 3rd value => adjacent
    // duplicate => mn < 256 => exact fallback (same proof as R9).
    float fA0 = __int_as_float(cA0), fA1 = __int_as_float(cA1), fA2 = __int_as_float(cA2);
    float fB0 = __int_as_float(cB0), fB1 = __int_as_float(cB1), fB2 = __int_as_float(cB2);
    unsigned mnA = 0xFFFFFFFFu, mnB = 0xFFFFFFFFu;
    int keepA = 0, keepB = 0, prevA = 0, prevB = 0;
#pragma unroll
    for (int r = 0; r < TOPK; r++) {
        int a = __reduce_max_sync(FULL, __float_as_int(fA0));
        int b = __reduce_max_sync(FULL, __float_as_int(fB0));
        keepA = (lane == r)     ? a : keepA;
        keepB = (lane == r + 8) ? b : keepB;
        if (r > 0) {
            mnA = min(mnA, (unsigned)(prevA ^ a));
            mnB = min(mnB, (unsigned)(prevB ^ b));
        }
        prevA = a; prevB = b;
        bool oA = (__float_as_int(fA0) == a);
        bool oB = (__float_as_int(fB0) == b);
        fA0 = oA ? fA1 : fA0;  fA1 = oA ? fA2 : fA1;
        fB0 = oB ? fB1 : fB0;  fB1 = oB ? fB2 : fB1;
    }
    {
        int a9 = __reduce_max_sync(FULL, __float_as_int(fA0));   // true 9th (boundary)
        int b9 = __reduce_max_sync(FULL, __float_as_int(fB0));
        mnA = min(mnA, (unsigned)(prevA ^ a9));
        mnB = min(mnB, (unsigned)(prevB ^ b9));
    }
    const bool okA = (mnA >= 256u);           // warp-uniform
    const bool okB = (mnB >= 256u);

    // ---- fast epilogue: token A on lanes 0-7, token B on lanes 8-15 ----
    if (lane < 16) {
        const int sub = lane & 7;
        const bool isB = (lane & 8) != 0;
        int g = (isB ? keepB : keepA) & 255;   // this lane's own kept winner

        const float* myrow = reinterpret_cast<const float*>(isB ? rowB4 : rowA4);
        float x = __ldg(myrow + g);            // L1-hot (row just streamed)
        float wgt = sigmoidf_fast(x);          // exact weight
        float sum = wgt;
#pragma unroll
        for (int off = 4; off; off >>= 1)
            sum += __shfl_xor_sync(0xFFFFu, sum, off);   // oct-local reduction
        float wn = wgt * __fdividef(1.0f, sum + 1e-20f);

        bool doStore = isB ? (okB && hasB) : okA;
        if (doStore) {
            size_t base = (size_t)(isB ? tokB : tokA) * TOPK + sub;
            out_idx[base] = (float)g;
            out_w [base] = wn;
        }
    }

    // ---- rare exact fallbacks (warp-uniform branches) ----
    if (!okA)
        exact_route_warp(reinterpret_cast<const float*>(rowA4), bias,
                         out_idx + (size_t)tokA * TOPK, out_w + (size_t)tokA * TOPK, lane);
    if (hasB && !okB)
        exact_route_warp(reinterpret_cast<const float*>(rowB4), bias,
                         out_idx + (size_t)tokB * TOPK, out_w + (size_t)tokB * TOPK, lane);
}

extern "C" void kernel_launch(void* const* d_in, const int* in_sizes, int n_in,
                              void* d_out, int out_size)
{
    const float* logits = (const float*)d_in[0];
    const float* bias   = (const float*)d_in[1];
    int T = in_sizes[0] / NUM_E;

    float* out_idx = (float*)d_out;
    float* out_w   = (float*)d_out + (size_t)T * TOPK;

    // 2 tokens per warp, 8 warps per block => 16 tokens per block
    const int threads = 256;
    const int blocks  = (T + 15) / 16;
    moe_route_kernel<<<blocks, threads>>>(logits, bias, out_idx, out_w, T);
}

// round 15
// speedup vs baseline: 1.0162x; 1.0162x over previous
#include <cuda_runtime.h>

#define FULL 0xFFFFFFFFu
#define NUM_E 256
#define TOPK 8

// monotonic float -> u32 key (fallback path only)
__device__ __forceinline__ unsigned f2key(float f) {
    unsigned u = __float_as_uint(f);
    return u ^ ((unsigned)((int)u >> 31) | 0x80000000u);
}
__device__ __forceinline__ float sigmoidf_fast(float x) {
    return __fdividef(1.0f, 1.0f + __expf(-x));
}

// Per-lane sorted top-3 keys for one token row (proven R9 network).
// Loads its own row data (R11 schedule: keeps peak register pressure ~40).
// key = raw float bits of (sigmoid+bias), low 8 bits = expert index
// g = (lane<<2) | (j&3) | ((j>>2)<<7)  (disjoint bit fields, unique, decode = &255)
__device__ __forceinline__ void build_top3(const float4* __restrict__ row4,
                                           float4 bb0, float4 bb1, int lane,
                                           int& c0, int& c1, int& c2)
{
    float4 x0 = row4[lane];
    float4 x1 = row4[lane + 32];
    float xs[8] = {x0.x, x0.y, x0.z, x0.w, x1.x, x1.y, x1.z, x1.w};
    float bs[8] = {bb0.x, bb0.y, bb0.z, bb0.w, bb1.x, bb1.y, bb1.z, bb1.w};
    const unsigned lane4 = (unsigned)lane << 2;
    int k[8];
#pragma unroll
    for (int j = 0; j < 8; j++) {
        float s = sigmoidf_fast(xs[j]);
        unsigned ub  = __float_as_uint(s + bs[j]);
        unsigned fld = lane4 | (unsigned)((j & 3) | ((j >> 2) << 7));
        k[j] = (int)((ub & 0xFFFFFF00u) | fld);
    }
#define PAIR(a, b) { int hi = max(k[a], k[b]); int lo = min(k[a], k[b]); k[a] = hi; k[b] = lo; }
    PAIR(0,1) PAIR(2,3) PAIR(4,5) PAIR(6,7)
#undef PAIR
    int a0, a1, a2, b0, b1, b2;
    {
        int h = max(k[0], k[2]), t = min(k[0], k[2]);
        a0 = h; a1 = max(k[1], t); a2 = max(min(k[1], t), k[3]);
    }
    {
        int h = max(k[4], k[6]), t = min(k[4], k[6]);
        b0 = h; b1 = max(k[5], t); b2 = max(min(k[5], t), k[7]);
    }
    c0 = max(a0, b2);
    c1 = max(a1, b1);
    c2 = max(a2, b0);
    { int a = c0, b = c1; c0 = max(a, b); c1 = min(a, b); }
    { int a = c0, b = c2; c0 = max(a, b); c2 = min(a, b); }
    { int a = c1, b = c2; c1 = max(a, b); c2 = min(a, b); }
}

// Proven exact fallback for one token (full-precision keys, Batcher + payload).
// Warp-uniform entry; rare (~0.4% of tokens).
__device__ void exact_route_warp(const float* __restrict__ rowp,
                                 const float* __restrict__ bias,
                                 float* __restrict__ oi,
                                 float* __restrict__ ow,
                                 int lane)
{
    const float4* row4 = reinterpret_cast<const float4*>(rowp);
    const float4* b4   = reinterpret_cast<const float4*>(bias);
    float4 y0 = row4[lane];              // L1/L2-hot reloads
    float4 y1 = row4[lane + 32];
    float4 cb0 = __ldg(b4 + lane);
    float4 cb1 = __ldg(b4 + lane + 32);
    float ys[8] = {y0.x, y0.y, y0.z, y0.w, y1.x, y1.y, y1.z, y1.w};
    float cs[8] = {cb0.x, cb0.y, cb0.z, cb0.w, cb1.x, cb1.y, cb1.z, cb1.w};

    unsigned fk[8], pj[8];
#pragma unroll
    for (int j = 0; j < 8; j++) {
        float s = sigmoidf_fast(ys[j]);
        fk[j] = f2key(s + cs[j]);
        pj[j] = (unsigned)j;
    }
#define CEP(a, b) do {                                    \
        unsigned ka = fk[a], kb = fk[b];                  \
        bool p = kb > ka;                                 \
        fk[a] = p ? kb : ka;  fk[b] = p ? ka : kb;        \
        unsigned pa = pj[a], pb = pj[b];                  \
        pj[a] = p ? pb : pa;  pj[b] = p ? pa : pb;        \
    } while (0)
    CEP(0,1); CEP(2,3); CEP(4,5); CEP(6,7);
    CEP(0,2); CEP(1,3); CEP(1,2);
    CEP(4,6); CEP(5,7); CEP(5,6);
    CEP(0,4); CEP(1,5); CEP(2,6); CEP(3,7);
    CEP(2,4); CEP(3,5);
    CEP(1,2); CEP(3,4); CEP(5,6);
#undef CEP
    unsigned pjpack = 0;
#pragma unroll
    for (int j = 0; j < 8; j++) pjpack |= pj[j] << (4 * j);

    int g = 0;
#pragma unroll
    for (int r = 0; r < TOPK; r++) {
        unsigned wb  = __reduce_max_sync(FULL, fk[0]);
        unsigned msk = __ballot_sync(FULL, fk[0] == wb);
        int src = __ffs(msk) - 1;

        int p0 = (int)(pjpack & 7u);
        int gg = 4 * lane + p0 + ((p0 & 4) ? 124 : 0);
        gg = __shfl_sync(FULL, gg, src);
        if (lane == r) g = gg;

        bool q = (lane == src);
        fk[0] = q ? fk[1] : fk[0];
        fk[1] = q ? fk[2] : fk[1];
        fk[2] = q ? fk[3] : fk[2];
        fk[3] = q ? fk[4] : fk[3];
        fk[4] = q ? fk[5] : fk[4];
        fk[5] = q ? fk[6] : fk[5];
        fk[6] = q ? fk[7] : fk[6];
        pjpack = q ? (pjpack >> 4) : pjpack;
    }

    if (lane < TOPK) {
        float x = __ldg(rowp + g);
        float wgt = sigmoidf_fast(x);
        float sum = wgt;
#pragma unroll
        for (int off = 4; off; off >>= 1)
            sum += __shfl_xor_sync(0xFFu, sum, off);
        float wn = wgt * __fdividef(1.0f, sum + 1e-20f);
        oi[lane] = (float)g;
        ow[lane] = wn;
    }
}

__global__ void __launch_bounds__(256, 6)   // ceiling 42 regs: stop ptxas ballooning,
                                            // above natural ~40 so no remat/spill
moe_route_kernel(const float* __restrict__ logits,
                 const float* __restrict__ bias,
                 float* __restrict__ out_idx,   // indices stored as float32 values
                 float* __restrict__ out_w,
                 int T)
{
    const int lane = threadIdx.x & 31;
    const int wgl  = (int)((blockIdx.x * blockDim.x + threadIdx.x) >> 5);
    const int tokA = 2 * wgl;
    const int tokB = tokA + 1;
    if (tokA >= T) return;                    // uniform per warp
    const bool hasB = (tokB < T);

    const float4* rowA4 = reinterpret_cast<const float4*>(logits) + (size_t)tokA * (NUM_E / 4);
    const float4* rowB4 = hasB ? rowA4 + (NUM_E / 4) : rowA4;    // safe dummy if odd T
    const float4* b4 = reinterpret_cast<const float4*>(bias);
    float4 bb0 = __ldg(b4 + lane);            // bias loaded once, serves both tokens
    float4 bb1 = __ldg(b4 + lane + 32);

    // ---- per-lane sorted top-3 for both tokens (R11 load schedule) ----
    int cA0, cA1, cA2, cB0, cB1, cB2;
    build_top3(rowA4, bb0, bb1, lane, cA0, cA1, cA2);
    build_top3(rowB4, bb0, bb1, lane, cB0, cB1, cB2);

    // ---- interleaved extraction: two independent REDUX chains overlap ----
    // In-loop keep: lane r holds token A's round-r winner, lane 8+r token B's.
    // Depth-2 chain: a lane's 4th win re-emits its 3rd value => adjacent
    // duplicate => mn < 256 => exact fallback (same proof as R9).
    float fA0 = __int_as_float(cA0), fA1 = __int_as_float(cA1), fA2 = __int_as_float(cA2);
    float fB0 = __int_as_float(cB0), fB1 = __int_as_float(cB1), fB2 = __int_as_float(cB2);
    unsigned mnA = 0xFFFFFFFFu, mnB = 0xFFFFFFFFu;
    int keepA = 0, keepB = 0, prevA = 0, prevB = 0;
#pragma unroll
    for (int r = 0; r < TOPK; r++) {
        int a = __reduce_max_sync(FULL, __float_as_int(fA0));
        int b = __reduce_max_sync(FULL, __float_as_int(fB0));
        keepA = (lane == r)     ? a : keepA;
        keepB = (lane == r + 8) ? b : keepB;
        if (r > 0) {
            mnA = min(mnA, (unsigned)(prevA ^ a));
            mnB = min(mnB, (unsigned)(prevB ^ b));
        }
        prevA = a; prevB = b;
        bool oA = (__float_as_int(fA0) == a);
        bool oB = (__float_as_int(fB0) == b);
        fA0 = oA ? fA1 : fA0;  fA1 = oA ? fA2 : fA1;
        fB0 = oB ? fB1 : fB0;  fB1 = oB ? fB2 : fB1;
    }
    {
        int a9 = __reduce_max_sync(FULL, __float_as_int(fA0));   // true 9th (boundary)
        int b9 = __reduce_max_sync(FULL, __float_as_int(fB0));
        mnA = min(mnA, (unsigned)(prevA ^ a9));
        mnB = min(mnB, (unsigned)(prevB ^ b9));
    }
    const bool okA = (mnA >= 256u);           // warp-uniform
    const bool okB = (mnB >= 256u);

    // ---- fast epilogue: token A on lanes 0-7, token B on lanes 8-15 ----
    if (lane < 16) {
        const int sub = lane & 7;
        const bool isB = (lane & 8) != 0;
        int g = (isB ? keepB : keepA) & 255;   // this lane's own kept winner

        const float* myrow = reinterpret_cast<const float*>(isB ? rowB4 : rowA4);
        float x = __ldg(myrow + g);            // L1-hot (row just streamed)
        float wgt = sigmoidf_fast(x);          // exact weight
        float sum = wgt;
#pragma unroll
        for (int off = 4; off; off >>= 1)
            sum += __shfl_xor_sync(0xFFFFu, sum, off);   // oct-local reduction
        float wn = wgt * __fdividef(1.0f, sum + 1e-20f);

        bool doStore = isB ? (okB && hasB) : okA;
        if (doStore) {
            size_t base = (size_t)(isB ? tokB : tokA) * TOPK + sub;
            out_idx[base] = (float)g;
            out_w [base] = wn;
        }
    }

    // ---- rare exact fallbacks (warp-uniform branches) ----
    if (!okA)
        exact_route_warp(reinterpret_cast<const float*>(rowA4), bias,
                         out_idx + (size_t)tokA * TOPK, out_w + (size_t)tokA * TOPK, lane);
    if (hasB && !okB)
        exact_route_warp(reinterpret_cast<const float*>(rowB4), bias,
                         out_idx + (size_t)tokB * TOPK, out_w + (size_t)tokB * TOPK, lane);
}

extern "C" void kernel_launch(void* const* d_in, const int* in_sizes, int n_in,
                              void* d_out, int out_size)
{
    const float* logits = (const float*)d_in[0];
    const float* bias   = (const float*)d_in[1];
    int T = in_sizes[0] / NUM_E;

    float* out_idx = (float*)d_out;
    float* out_w   = (float*)d_out + (size_t)T * TOPK;

    // 2 tokens per warp, 8 warps per block => 16 tokens per block
    const int threads = 256;
    const int blocks  = (T + 15) / 16;
    moe_route_kernel<<<blocks, threads>>>(logits, bias, out_idx, out_w, T);
}

// round 16
// speedup vs baseline: 1.1285x; 1.1105x over previous
#include <cuda_runtime.h>

#define FULL 0xFFFFFFFFu
#define NUM_E 256
#define TOPK 8

// monotonic float -> u32 key (fallback path only)
__device__ __forceinline__ unsigned f2key(float f) {
    unsigned u = __float_as_uint(f);
    return u ^ ((unsigned)((int)u >> 31) | 0x80000000u);
}
__device__ __forceinline__ float sigmoidf_fast(float x) {
    return __fdividef(1.0f, 1.0f + __expf(-x));
}

// Build per-lane sorted top-3 keys for one token row (R9's proven network).
// key = raw float bits of (sigmoid+bias), low 8 bits = expert index
// g = (lane<<2) | (j&3) | ((j>>2)<<7)  (disjoint bit fields, unique, decode = &255)
__device__ __forceinline__ void build_top3(const float4* __restrict__ row4,
                                           float4 bb0, float4 bb1, int lane,
                                           int& c0, int& c1, int& c2)
{
    float4 x0 = row4[lane];
    float4 x1 = row4[lane + 32];
    float xs[8] = {x0.x, x0.y, x0.z, x0.w, x1.x, x1.y, x1.z, x1.w};
    float bs[8] = {bb0.x, bb0.y, bb0.z, bb0.w, bb1.x, bb1.y, bb1.z, bb1.w};
    const unsigned lane4 = (unsigned)lane << 2;
    int k[8];
#pragma unroll
    for (int j = 0; j < 8; j++) {
        float s = sigmoidf_fast(xs[j]);
        unsigned ub  = __float_as_uint(s + bs[j]);
        unsigned fld = lane4 | (unsigned)((j & 3) | ((j >> 2) << 7));
        k[j] = (int)((ub & 0xFFFFFF00u) | fld);
    }
#define PAIR(a, b) { int hi = max(k[a], k[b]); int lo = min(k[a], k[b]); k[a] = hi; k[b] = lo; }
    PAIR(0,1) PAIR(2,3) PAIR(4,5) PAIR(6,7)
#undef PAIR
    int a0, a1, a2, b0, b1, b2;
    {
        int h = max(k[0], k[2]), t = min(k[0], k[2]);
        a0 = h; a1 = max(k[1], t); a2 = max(min(k[1], t), k[3]);
    }
    {
        int h = max(k[4], k[6]), t = min(k[4], k[6]);
        b0 = h; b1 = max(k[5], t); b2 = max(min(k[5], t), k[7]);
    }
    c0 = max(a0, b2);
    c1 = max(a1, b1);
    c2 = max(a2, b0);
    { int a = c0, b = c1; c0 = max(a, b); c1 = min(a, b); }
    { int a = c0, b = c2; c0 = max(a, b); c2 = min(a, b); }
    { int a = c1, b = c2; c1 = max(a, b); c2 = min(a, b); }
}

// R9's proven exact fallback for one token: full-precision keys, Batcher sort
// with payload, ballot/shfl extraction, exact epilogue. Warp-uniform entry.
__device__ void exact_route_warp(const float* __restrict__ rowp,
                                 const float* __restrict__ bias,
                                 float* __restrict__ oi,
                                 float* __restrict__ ow,
                                 int lane)
{
    const float4* row4 = reinterpret_cast<const float4*>(rowp);
    const float4* b4   = reinterpret_cast<const float4*>(bias);
    float4 y0 = row4[lane];              // L1/L2-hot reloads
    float4 y1 = row4[lane + 32];
    float4 cb0 = __ldg(b4 + lane);
    float4 cb1 = __ldg(b4 + lane + 32);
    float ys[8] = {y0.x, y0.y, y0.z, y0.w, y1.x, y1.y, y1.z, y1.w};
    float cs[8] = {cb0.x, cb0.y, cb0.z, cb0.w, cb1.x, cb1.y, cb1.z, cb1.w};

    unsigned fk[8], pj[8];
#pragma unroll
    for (int j = 0; j < 8; j++) {
        float s = sigmoidf_fast(ys[j]);
        fk[j] = f2key(s + cs[j]);
        pj[j] = (unsigned)j;
    }
#define CEP(a, b) do {                                    \
        unsigned ka = fk[a], kb = fk[b];                  \
        bool p = kb > ka;                                 \
        fk[a] = p ? kb : ka;  fk[b] = p ? ka : kb;        \
        unsigned pa = pj[a], pb = pj[b];                  \
        pj[a] = p ? pb : pa;  pj[b] = p ? pa : pb;        \
    } while (0)
    CEP(0,1); CEP(2,3); CEP(4,5); CEP(6,7);
    CEP(0,2); CEP(1,3); CEP(1,2);
    CEP(4,6); CEP(5,7); CEP(5,6);
    CEP(0,4); CEP(1,5); CEP(2,6); CEP(3,7);
    CEP(2,4); CEP(3,5);
    CEP(1,2); CEP(3,4); CEP(5,6);
#undef CEP
    unsigned pjpack = 0;
#pragma unroll
    for (int j = 0; j < 8; j++) pjpack |= pj[j] << (4 * j);

    int g = 0;
#pragma unroll
    for (int r = 0; r < TOPK; r++) {
        unsigned wb  = __reduce_max_sync(FULL, fk[0]);
        unsigned msk = __ballot_sync(FULL, fk[0] == wb);
        int src = __ffs(msk) - 1;

        int p0 = (int)(pjpack & 7u);
        int gg = 4 * lane + p0 + ((p0 & 4) ? 124 : 0);
        gg = __shfl_sync(FULL, gg, src);
        if (lane == r) g = gg;

        bool q = (lane == src);
        fk[0] = q ? fk[1] : fk[0];
        fk[1] = q ? fk[2] : fk[1];
        fk[2] = q ? fk[3] : fk[2];
        fk[3] = q ? fk[4] : fk[3];
        fk[4] = q ? fk[5] : fk[4];
        fk[5] = q ? fk[6] : fk[5];
        fk[6] = q ? fk[7] : fk[6];
        pjpack = q ? (pjpack >> 4) : pjpack;
    }

    if (lane < TOPK) {
        float x = __ldg(rowp + g);
        float wgt = sigmoidf_fast(x);
        float sum = wgt;
#pragma unroll
        for (int off = 4; off; off >>= 1)
            sum += __shfl_xor_sync(0xFFu, sum, off);
        float wn = wgt * __fdividef(1.0f, sum + 1e-20f);
        oi[lane] = (float)g;
        ow[lane] = wn;
    }
}

__global__ void __launch_bounds__(256)
moe_route_kernel(const float* __restrict__ logits,
                 const float* __restrict__ bias,
                 float* __restrict__ out_idx,   // indices stored as float32 values
                 float* __restrict__ out_w,
                 int T)
{
    const int lane = threadIdx.x & 31;
    const int wgl  = (int)((blockIdx.x * blockDim.x + threadIdx.x) >> 5);
    const int tokA = 2 * wgl;
    const int tokB = tokA + 1;
    if (tokA >= T) return;                    // uniform per warp
    const bool hasB = (tokB < T);

    const float4* rowA4 = reinterpret_cast<const float4*>(logits) + (size_t)tokA * (NUM_E / 4);
    const float4* rowB4 = hasB ? rowA4 + (NUM_E / 4) : rowA4;    // safe dummy if odd T
    const float4* b4 = reinterpret_cast<const float4*>(bias);
    float4 bb0 = __ldg(b4 + lane);            // bias loaded once, serves both tokens
    float4 bb1 = __ldg(b4 + lane + 32);

    // ---- build per-lane sorted top-3 for both tokens (loads overlap, MLP=4) ----
    int cA0, cA1, cA2, cB0, cB1, cB2;
    build_top3(rowA4, bb0, bb1, lane, cA0, cA1, cA2);
    build_top3(rowB4, bb0, bb1, lane, cB0, cB1, cB2);

    // ---- interleaved extraction: two independent REDUX chains overlap ----
    // Depth-2 chain per token; a lane's 4th win re-emits its 3rd value =>
    // adjacent duplicate => mn < 256 => exact fallback (same proof as R9).
    float fA0 = __int_as_float(cA0), fA1 = __int_as_float(cA1), fA2 = __int_as_float(cA2);
    float fB0 = __int_as_float(cB0), fB1 = __int_as_float(cB1), fB2 = __int_as_float(cB2);
    int wA[8], wB[8];
    unsigned mnA = 0xFFFFFFFFu, mnB = 0xFFFFFFFFu;
    int prevA = 0, prevB = 0;
#pragma unroll
    for (int r = 0; r < TOPK; r++) {
        int a = __reduce_max_sync(FULL, __float_as_int(fA0));
        int b = __reduce_max_sync(FULL, __float_as_int(fB0));
        wA[r] = a; wB[r] = b;
        if (r > 0) {
            mnA = min(mnA, (unsigned)(prevA ^ a));
            mnB = min(mnB, (unsigned)(prevB ^ b));
        }
        prevA = a; prevB = b;
        bool oA = (__float_as_int(fA0) == a);
        bool oB = (__float_as_int(fB0) == b);
        fA0 = oA ? fA1 : fA0;  fA1 = oA ? fA2 : fA1;
        fB0 = oB ? fB1 : fB0;  fB1 = oB ? fB2 : fB1;
    }
    {
        int a9 = __reduce_max_sync(FULL, __float_as_int(fA0));   // true 9th (boundary)
        int b9 = __reduce_max_sync(FULL, __float_as_int(fB0));
        mnA = min(mnA, (unsigned)(prevA ^ a9));
        mnB = min(mnB, (unsigned)(prevB ^ b9));
    }
    const bool okA = (mnA >= 256u);           // warp-uniform
    const bool okB = (mnB >= 256u);

    // ---- fast epilogue: token A on lanes 0-7, token B on lanes 8-15 ----
    if (lane < 16) {
        const int sub = lane & 7;
        const bool isB = (lane & 8) != 0;
        // keep = w{A,B}[sub] via select tree over REDUX broadcast values
        int v0 = isB ? wB[0] : wA[0], v1 = isB ? wB[1] : wA[1];
        int v2 = isB ? wB[2] : wA[2], v3 = isB ? wB[3] : wA[3];
        int v4 = isB ? wB[4] : wA[4], v5 = isB ? wB[5] : wA[5];
        int v6 = isB ? wB[6] : wA[6], v7 = isB ? wB[7] : wA[7];
        int s0 = (sub & 1) ? v1 : v0;
        int s1 = (sub & 1) ? v3 : v2;
        int s2 = (sub & 1) ? v5 : v4;
        int s3 = (sub & 1) ? v7 : v6;
        int u0 = (sub & 2) ? s1 : s0;
        int u1 = (sub & 2) ? s3 : s2;
        int g = ((sub & 4) ? u1 : u0) & 255;   // expert index embedded in key

        const float* myrow = reinterpret_cast<const float*>(isB ? rowB4 : rowA4);
        float x = __ldg(myrow + g);            // L1-hot (row just streamed)
        float wgt = sigmoidf_fast(x);          // exact weight
        float sum = wgt;
#pragma unroll
        for (int off = 4; off; off >>= 1)
            sum += __shfl_xor_sync(0xFFFFu, sum, off);   // oct-local (stays in 0-7 / 8-15)
        float wn = wgt * __fdividef(1.0f, sum + 1e-20f);

        bool doStore = isB ? (okB && hasB) : okA;
        if (doStore) {
            size_t base = (size_t)(isB ? tokB : tokA) * TOPK + sub;
            out_idx[base] = (float)g;
            out_w [base] = wn;
        }
    }

    // ---- rare exact fallbacks (warp-uniform branches) ----
    if (!okA)
        exact_route_warp(reinterpret_cast<const float*>(rowA4), bias,
                         out_idx + (size_t)tokA * TOPK, out_w + (size_t)tokA * TOPK, lane);
    if (hasB && !okB)
        exact_route_warp(reinterpret_cast<const float*>(rowB4), bias,
                         out_idx + (size_t)tokB * TOPK, out_w + (size_t)tokB * TOPK, lane);
}

extern "C" void kernel_launch(void* const* d_in, const int* in_sizes, int n_in,
                              void* d_out, int out_size)
{
    const float* logits = (const float*)d_in[0];
    const float* bias   = (const float*)d_in[1];
    int T = in_sizes[0] / NUM_E;

    float* out_idx = (float*)d_out;
    float* out_w   = (float*)d_out + (size_t)T * TOPK;

    // 2 tokens per warp, 8 warps per block => 16 tokens per block
    const int threads = 256;
    const int blocks  = (T + 15) / 16;
    moe_route_kernel<<<blocks, threads>>>(logits, bias, out_idx, out_w, T);
}